// round 13
// baseline (speedup 1.0000x reference)
#include <cuda_runtime.h>
#include <cstdint>

// ============================================================================
// LSTM_34883724378521 : T=60, C=H=128, N=4096, TOUT=114
// Fused tf32 mma.sync step kernels (no Z materialization).
// CTA tile M=128 x N=64, 256 threads, grid (8 x 32) = 256 CTAs -> 2 CTAs/SM.
// K=64 chunks (phase-1: 4 chunks = h,h,img,img; phase-2: 2 chunks) to halve
// chunk-boundary overhead. Phase-1 prefetches img[t+1] into L2.
// ============================================================================
#define NB 4096
#define HD 128
#define NG 512

__device__ __forceinline__ uint32_t smem_u32(const void* p) {
    uint32_t a;
    asm("{ .reg .u64 t; cvta.to.shared.u64 t, %1; cvt.u32.u64 %0, t; }"
        : "=r"(a) : "l"(p));
    return a;
}
__device__ __forceinline__ void cp16(uint32_t dst, const void* src) {
    asm volatile("cp.async.cg.shared.global [%0], [%1], 16;" :: "r"(dst), "l"(src));
}
#define CP_COMMIT() asm volatile("cp.async.commit_group;" ::: "memory")
#define CP_WAIT(n)  asm volatile("cp.async.wait_group %0;" :: "n"(n) : "memory")

__device__ __forceinline__ uint32_t rna_tf32(float v) {
    uint32_t u; asm("cvt.rna.tf32.f32 %0, %1;" : "=r"(u) : "f"(v)); return u;
}
__device__ __forceinline__ void mma8(float* d, const uint32_t* a, const uint32_t* b) {
    asm volatile(
        "mma.sync.aligned.m16n8k8.row.col.f32.tf32.tf32.f32 "
        "{%0,%1,%2,%3}, {%4,%5,%6,%7}, {%8,%9}, {%0,%1,%2,%3};"
        : "+f"(d[0]), "+f"(d[1]), "+f"(d[2]), "+f"(d[3])
        : "r"(a[0]), "r"(a[1]), "r"(a[2]), "r"(a[3]), "r"(b[0]), "r"(b[1]));
}
__device__ __forceinline__ float sigf(float x)   { return 1.0f / (1.0f + __expf(-x)); }
__device__ __forceinline__ float tanhf_(float x) { return 1.0f - 2.0f / (__expf(2.0f * x) + 1.0f); }

// ---------------------------------------------------------------------------
// persistent device state
// ---------------------------------------------------------------------------
__device__ float g_Hbuf0[HD * NB];   // h state, h-major [H][N] (tf32-rounded)
__device__ float g_Hbuf1[HD * NB];
__device__ float g_Cbuf [HD * NB];   // c state, h-major
__device__ float g_W1[NG * 256];     // permuted [4h+g][h|x]  (h cols first)
__device__ float g_W2[NG * 128];     // permuted (W_ih+W_hh), tf32-rounded
__device__ float g_bias[NG];         // permuted b_ih + b_hh

// ---------------------------------------------------------------------------
// prep: row perm r = 4*h+g <- g*128+h. W1 cols: k<128 -> W_hh (h part first),
// k>=128 -> W_ih (img). RNA-round; zero state. (identical to round-9)
// ---------------------------------------------------------------------------
__global__ void prep_kernel(const float* __restrict__ Wih, const float* __restrict__ Whh,
                            const float* __restrict__ bih, const float* __restrict__ bhh) {
    int tid = blockIdx.x * 256 + threadIdx.x;       // 512*256 = 131072
    int r = tid >> 8, k = tid & 255;
    int h = r >> 2, g = r & 3;
    int orig = g * HD + h;
    float v = (k < 128) ? Whh[orig * HD + k] : Wih[orig * HD + (k - 128)];
    g_W1[r * 256 + k] = __uint_as_float(rna_tf32(v));
    if (k < 128)
        g_W2[r * 128 + k] =
            __uint_as_float(rna_tf32(Wih[orig * HD + k] + Whh[orig * HD + k]));
    if (k == 0) g_bias[r] = bih[orig] + bhh[orig];
    for (int i = tid; i < HD * NB; i += 131072) {
        g_Hbuf0[i] = 0.0f;
        g_Cbuf[i]  = 0.0f;
    }
}

// ---------------------------------------------------------------------------
// smem layout (float offsets): bias(64) | 2x A(64x136) | 2x B(64x68)
// H2 stage (16 x 130) aliases A buffer 0 after the mainloop.
// ---------------------------------------------------------------------------
static constexpr int A_STR = 136, B_STR = 68, H_STR = 130;
static constexpr int A_FL  = 64 * A_STR;      // 8704
static constexpr int B_FL  = 64 * B_STR;      // 4352
static constexpr int OFF_BIAS = 0;
static constexpr int OFF_A    = 64;
static constexpr int OFF_B    = OFF_A + 2 * A_FL;
static constexpr int SM_FLOATS = OFF_B + 2 * B_FL;   // 26176
static constexpr int SM_BYTES  = SM_FLOATS * 4;      // 104704 -> 2 CTAs/SM

// ---------------------------------------------------------------------------
// fused step. CTA tile M=128 x N=64 (16 hidden units), K = NCH*64.
// NCH=4: chunks 0-1 = h (W_hh cols), 2-3 = img (W_ih cols). NCH=2: h only.
// ---------------------------------------------------------------------------
template <int NCH>
__global__ void __launch_bounds__(256, 2)
lstm_step(const float* __restrict__ xsrc,     // [128][NB] x_t slice or null
          const float* __restrict__ imgnext,  // img[t+1] slice for L2 prefetch
          const float* __restrict__ hprev,    // [128][NB] (pre-rounded tf32)
          float* __restrict__ hnext,
          float* __restrict__ out, int t_out, int TOUT) {
    extern __shared__ float smf[];
    const uint32_t sb = smem_u32(smf);
    const int tid = threadIdx.x, lane = tid & 31, wid = tid >> 5;
    const int gq = lane >> 2, tig = lane & 3;
    const int wm = wid >> 1, wn = wid & 1;            // 4 x 2 warp grid
    const int j = blockIdx.x, n0 = blockIdx.y * 128;  // j: 64 gate cols

    if (tid < 64) smf[OFF_BIAS + tid] = g_bias[j * 64 + tid];

    const float* W = (NCH == 4) ? g_W1 : g_W2;
    const int KT = NCH * 64;

    auto loadC = [&](int ch) {
        const int buf = ch & 1;
        const float* asrc = (NCH == 4 && ch >= 2) ? xsrc : hprev;
        const int kr = (NCH == 4 && ch >= 2) ? (ch - 2) * 64 : ch * 64;
        const uint32_t ab = sb + (uint32_t)(OFF_A + buf * A_FL) * 4;
        const uint32_t bb = sb + (uint32_t)(OFF_B + buf * B_FL) * 4;
        #pragma unroll
        for (int it = 0; it < 8; it++) {   // A: 64 k-rows x 128 m
            int idx = tid + it * 256;
            int kk = idx >> 5, mp = (idx & 31) << 2;
            cp16(ab + (uint32_t)(kk * A_STR + mp) * 4,
                 asrc + (size_t)(kr + kk) * NB + n0 + mp);
        }
        #pragma unroll
        for (int it = 0; it < 4; it++) {   // B: 64 gate-cols x 64 k
            int idx = tid + it * 256;
            int n = idx >> 4, q = (idx & 15) << 2;
            cp16(bb + (uint32_t)(n * B_STR + q) * 4,
                 W + (size_t)(j * 64 + n) * KT + ch * 64 + q);
        }
        CP_COMMIT();
    };

    float acc[2][4][4];
    #pragma unroll
    for (int a0 = 0; a0 < 2; a0++)
        #pragma unroll
        for (int a1 = 0; a1 < 4; a1++)
            #pragma unroll
            for (int a2 = 0; a2 < 4; a2++) acc[a0][a1][a2] = 0.0f;

    loadC(0);

    // L2 prefetch of the NEXT step's img slice (2 MB / 65536 threads = 32 B)
    if (NCH == 4 && imgnext != nullptr) {
        const size_t off =
            ((size_t)(blockIdx.y * 8 + blockIdx.x) * 256 + tid) * 8;
        asm volatile("prefetch.global.L2 [%0];" :: "l"(imgnext + off));
    }

    #pragma unroll
    for (int ch = 0; ch < NCH; ch++) {
        CP_WAIT(0);
        __syncthreads();                   // chunk ch ready; mma(ch-1) done
        if (ch + 1 < NCH) loadC(ch + 1);   // writes drained buf (ch+1)&1
        const float* As = smf + OFF_A + (ch & 1) * A_FL;
        const float* Bs = smf + OFF_B + (ch & 1) * B_FL;
        const bool docvt = (NCH == 4 && ch >= 2);   // img chunks need rounding

        #pragma unroll
        for (int kc = 0; kc < 8; kc++) {
            const int k0 = kc * 8;
            uint32_t a[2][4];
            #pragma unroll
            for (int mt = 0; mt < 2; mt++) {
                const int r0 = wm * 32 + mt * 16 + gq;
                float v0 = As[(k0 + tig) * A_STR + r0];
                float v1 = As[(k0 + tig) * A_STR + r0 + 8];
                float v2 = As[(k0 + tig + 4) * A_STR + r0];
                float v3 = As[(k0 + tig + 4) * A_STR + r0 + 8];
                if (docvt) {
                    a[mt][0] = rna_tf32(v0); a[mt][1] = rna_tf32(v1);
                    a[mt][2] = rna_tf32(v2); a[mt][3] = rna_tf32(v3);
                } else {
                    a[mt][0] = __float_as_uint(v0); a[mt][1] = __float_as_uint(v1);
                    a[mt][2] = __float_as_uint(v2); a[mt][3] = __float_as_uint(v3);
                }
            }
            #pragma unroll
            for (int nt = 0; nt < 4; nt++) {
                const int c0 = wn * 32 + nt * 8 + gq;
                uint32_t b[2];
                b[0] = __float_as_uint(Bs[c0 * B_STR + k0 + tig]);
                b[1] = __float_as_uint(Bs[c0 * B_STR + k0 + tig + 4]);
                mma8(acc[0][nt], a[0], b);
                mma8(acc[1][nt], a[1], b);
            }
        }
    }
    __syncthreads();     // all mma done -> A bufs reusable as H2 stage

    // ---- shuffle epilogue: pair (i,f) with (g,o) via lane^1 ----
    float* H2 = smf + OFF_A;            // 16 units x H_STR
    const int mymt = tig & 1;
    const int r0e = wm * 32 + mymt * 16 + gq;
    #pragma unroll
    for (int nt = 0; nt < 4; nt++) {
        const int u = wn * 8 + nt * 2 + (tig >> 1);
        float oth[4];
        #pragma unroll
        for (int e = 0; e < 4; e++)
            oth[e] = __shfl_xor_sync(0xffffffffu, acc[mymt ^ 1][nt][e], 1);
        const float b0 = smf[OFF_BIAS + 4 * u + 0];
        const float b1 = smf[OFF_BIAS + 4 * u + 1];
        const float b2 = smf[OFF_BIAS + 4 * u + 2];
        const float b3 = smf[OFF_BIAS + 4 * u + 3];
        #pragma unroll
        for (int e2 = 0; e2 < 2; e2++) {
            const float ow0 = acc[mymt][nt][2 * e2], ow1 = acc[mymt][nt][2 * e2 + 1];
            const float ot0 = oth[2 * e2],           ot1 = oth[2 * e2 + 1];
            float gi, gf, gg, go;
            if (mymt == 0) { gi = ow0; gf = ow1; gg = ot0; go = ot1; }
            else           { gg = ow0; go = ow1; gi = ot0; gf = ot1; }
            gi += b0; gf += b1; gg += b2; go += b3;
            const int row = r0e + 8 * e2;
            const size_t ci = (size_t)(j * 16 + u) * NB + n0 + row;
            const float cold = g_Cbuf[ci];
            const float cn = sigf(gf) * cold + sigf(gi) * tanhf_(gg);
            g_Cbuf[ci] = cn;
            H2[u * H_STR + row] = sigf(go) * tanhf_(cn);
        }
    }
    __syncthreads();

    // ---- h-state writeback (h-major, pre-rounded to tf32) ----
    #pragma unroll
    for (int q = 0; q < 2; q++) {
        const int u = wid * 2 + q;
        #pragma unroll
        for (int mk = 0; mk < 4; mk++) {
            const int m = mk * 32 + lane;
            hnext[(size_t)(j * 16 + u) * NB + n0 + m] =
                __uint_as_float(rna_tf32(H2[u * H_STR + m]));
        }
    }
    // ---- output: out[n][t][h], 64B contiguous (16 h per CTA) ----
    const int hh = lane & 15, rp = lane >> 4;
    #pragma unroll
    for (int i2 = 0; i2 < 8; i2++) {
        const int mr = wid * 16 + i2 * 2 + rp;
        out[(size_t)(n0 + mr) * TOUT * HD + (size_t)t_out * HD + j * 16 + hh] =
            H2[hh * H_STR + mr];
    }
}

// ---------------------------------------------------------------------------
// launch: prep + 60 K=256 steps + 54 K=128 steps
// ---------------------------------------------------------------------------
extern "C" void kernel_launch(void* const* d_in, const int* in_sizes, int n_in,
                              void* d_out, int out_size) {
    const float* img = (const float*)d_in[0];
    const float* Wih = (const float*)d_in[2];
    const float* Whh = (const float*)d_in[3];
    const float* bih = (const float*)d_in[4];
    const float* bhh = (const float*)d_in[5];
    float* out = (float*)d_out;

    const int T    = in_sizes[0] / (HD * NB);       // 60
    const int TOUT = out_size / (NB * HD);          // 114

    void *h0p, *h1p;
    cudaGetSymbolAddress(&h0p, g_Hbuf0);
    cudaGetSymbolAddress(&h1p, g_Hbuf1);
    float* hb[2] = {(float*)h0p, (float*)h1p};

    cudaFuncSetAttribute((const void*)lstm_step<4>,
                         cudaFuncAttributeMaxDynamicSharedMemorySize, SM_BYTES);
    cudaFuncSetAttribute((const void*)lstm_step<2>,
                         cudaFuncAttributeMaxDynamicSharedMemorySize, SM_BYTES);

    prep_kernel<<<512, 256>>>(Wih, Whh, bih, bhh);

    dim3 grid(8, NB / 128);                         // 256 CTAs, 2/SM
    for (int t = 0; t < TOUT; t++) {
        float* hp = hb[t & 1];
        float* hn = hb[(t + 1) & 1];
        if (t < T) {
            const float* nxt = (t + 1 < T) ? img + (size_t)(t + 1) * HD * NB
                                           : nullptr;
            lstm_step<4><<<grid, 256, SM_BYTES>>>(
                img + (size_t)t * HD * NB, nxt, hp, hn, out, t, TOUT);
        } else {
            lstm_step<2><<<grid, 256, SM_BYTES>>>(
                nullptr, nullptr, hp, hn, out, t, TOUT);
        }
    }
}

// round 14
// speedup vs baseline: 1.4684x; 1.4684x over previous
#include <cuda_runtime.h>
#include <cstdint>

// ============================================================================
// LSTM_34883724378521 : T=60, C=H=128, N=4096, TOUT=114
// Phase-1 kernel fuses TWO halves per CTA:
//   (a) recurrent step t:  gates = h @ W_hh^T + Z[t&1] + b  (Z is L2-hot,
//       written by the previous kernel)  -> cell update -> writebacks
//   (b) zprep for t+1:     Z[(t+1)&1] = img[t+1] @ W_ih^T   (independent,
//       runs in cross-CTA slack; consumed only after the kernel boundary)
// Phase-2: gates = h @ (W_ih+W_hh)^T + b  (proven 2.9us step).
// tf32 mma.sync, CTA tile M=128 x N=64, 256 threads, 2 CTAs/SM, grid (8,32).
// ============================================================================
#define NB 4096
#define HD 128
#define NG 512

__device__ __forceinline__ uint32_t smem_u32(const void* p) {
    uint32_t a;
    asm("{ .reg .u64 t; cvta.to.shared.u64 t, %1; cvt.u32.u64 %0, t; }"
        : "=r"(a) : "l"(p));
    return a;
}
__device__ __forceinline__ void cp16(uint32_t dst, const void* src) {
    asm volatile("cp.async.cg.shared.global [%0], [%1], 16;" :: "r"(dst), "l"(src));
}
#define CP_COMMIT() asm volatile("cp.async.commit_group;" ::: "memory")
#define CP_WAIT(n)  asm volatile("cp.async.wait_group %0;" :: "n"(n) : "memory")

__device__ __forceinline__ uint32_t rna_tf32(float v) {
    uint32_t u; asm("cvt.rna.tf32.f32 %0, %1;" : "=r"(u) : "f"(v)); return u;
}
__device__ __forceinline__ void mma8(float* d, const uint32_t* a, const uint32_t* b) {
    asm volatile(
        "mma.sync.aligned.m16n8k8.row.col.f32.tf32.tf32.f32 "
        "{%0,%1,%2,%3}, {%4,%5,%6,%7}, {%8,%9}, {%0,%1,%2,%3};"
        : "+f"(d[0]), "+f"(d[1]), "+f"(d[2]), "+f"(d[3])
        : "r"(a[0]), "r"(a[1]), "r"(a[2]), "r"(a[3]), "r"(b[0]), "r"(b[1]));
}
__device__ __forceinline__ float sigf(float x)   { return 1.0f / (1.0f + __expf(-x)); }
__device__ __forceinline__ float tanhf_(float x) { return 1.0f - 2.0f / (__expf(2.0f * x) + 1.0f); }

// ---------------------------------------------------------------------------
// persistent device state
// ---------------------------------------------------------------------------
__device__ float g_Hbuf0[HD * NB];     // h state, h-major [H][N] (tf32-rounded)
__device__ float g_Hbuf1[HD * NB];
__device__ float g_Cbuf [HD * NB];     // c state, h-major
__device__ float g_Whh[NG * HD];       // permuted W_hh, tf32-rounded
__device__ float g_Wih[NG * HD];       // permuted W_ih, tf32-rounded
__device__ float g_Wsum[NG * HD];      // permuted W_ih+W_hh, tf32-rounded
__device__ float g_bias[NG];           // permuted b_ih + b_hh
__device__ float g_Z[2 * NG * NB];     // 16.8 MB ring: x@W_ih^T, 2 slots

// ---------------------------------------------------------------------------
// prep: row perm r = 4*h+g <- g*128+h ; RNA-round weights; zero state
// ---------------------------------------------------------------------------
__global__ void prep_kernel(const float* __restrict__ Wih, const float* __restrict__ Whh,
                            const float* __restrict__ bih, const float* __restrict__ bhh) {
    int tid = blockIdx.x * 256 + threadIdx.x;       // 256*256 = 65536
    int r = tid >> 7, k = tid & 127;
    int h = r >> 2, g = r & 3;
    int orig = g * HD + h;
    float wi = Wih[orig * HD + k], wh = Whh[orig * HD + k];
    g_Wih [r * HD + k] = __uint_as_float(rna_tf32(wi));
    g_Whh [r * HD + k] = __uint_as_float(rna_tf32(wh));
    g_Wsum[r * HD + k] = __uint_as_float(rna_tf32(wi + wh));
    if (k == 0) g_bias[r] = bih[orig] + bhh[orig];
    for (int i = tid; i < HD * NB; i += 65536) {
        g_Hbuf0[i] = 0.0f;
        g_Cbuf[i]  = 0.0f;
    }
}

// ---------------------------------------------------------------------------
// smem layout (float offsets): bias(64) | 2x A(32x136) | 2x B(64x36) | Z(64x132)
// H2 stage (16 x 130) aliases A buffer 0 after the step mainloop.
// ---------------------------------------------------------------------------
static constexpr int A_STR = 136, B_STR = 36, H_STR = 130, Z_STR = 132;
static constexpr int A_FL  = 32 * A_STR;      // 4352
static constexpr int B_FL  = 64 * B_STR;      // 2304
static constexpr int OFF_BIAS = 0;
static constexpr int OFF_A    = 64;
static constexpr int OFF_B    = OFF_A + 2 * A_FL;     // 8768
static constexpr int OFF_Z    = OFF_B + 2 * B_FL;     // 13376
static constexpr int SM_FLOATS = OFF_Z + 64 * Z_STR;  // 21824
static constexpr int SM_BYTES  = SM_FLOATS * 4;       // 87296 -> 2 CTAs/SM

// ---------------------------------------------------------------------------
// shared mainloop: 4 chunks of K=32, 2 A bufs / 2 B bufs, prefetch dist 1.
// A from asrc [128][NB] at col n0 (DOCVT: round to tf32); B from W [NG][128].
// (verbatim from the round-11 passing kernel)
// ---------------------------------------------------------------------------
template <bool DOCVT, bool HASZ>
__device__ __forceinline__ void gemm_mainloop(
    float acc[2][4][4], float* smf, uint32_t sb,
    const float* asrc, const float* W, const float* zt,
    int j, int n0, int tid, int wm, int wn, int gq, int tig) {

    auto loadC = [&](int ch) {
        const int buf = ch & 1;
        const uint32_t ab = sb + (uint32_t)(OFF_A + buf * A_FL) * 4;
        const uint32_t bb = sb + (uint32_t)(OFF_B + buf * B_FL) * 4;
        #pragma unroll
        for (int it = 0; it < 4; it++) {   // A: 32 k-rows x 128 m
            int idx = tid + it * 256;
            int kk = idx >> 5, mp = (idx & 31) << 2;
            cp16(ab + (uint32_t)(kk * A_STR + mp) * 4,
                 asrc + (size_t)(ch * 32 + kk) * NB + n0 + mp);
        }
        #pragma unroll
        for (int it = 0; it < 2; it++) {   // B: 64 gate-cols x 32 k
            int idx = tid + it * 256;
            int n = idx >> 3, q = (idx & 7) << 2;
            cp16(bb + (uint32_t)(n * B_STR + q) * 4,
                 W + (size_t)(j * 64 + n) * HD + ch * 32 + q);
        }
        CP_COMMIT();
    };

    loadC(0);
    if (HASZ) {                            // Z tile: 64 c-rows x 128 n (L2-hot)
        #pragma unroll
        for (int it = 0; it < 8; it++) {
            int idx = tid + it * 256;
            int row = idx >> 5, q = (idx & 31) << 2;
            cp16(sb + (uint32_t)(OFF_Z + row * Z_STR + q) * 4,
                 zt + (size_t)row * NB + q);
        }
        CP_COMMIT();
    }

    #pragma unroll
    for (int ch = 0; ch < 4; ch++) {
        if (ch == 0 && HASZ) { CP_WAIT(1); } else { CP_WAIT(0); }
        __syncthreads();                   // chunk ch ready; mma(ch-1) done
        if (ch + 1 < 4) loadC(ch + 1);     // writes buf (ch+1)&1 (drained)
        const float* As = smf + OFF_A + (ch & 1) * A_FL;
        const float* Bs = smf + OFF_B + (ch & 1) * B_FL;

        #pragma unroll
        for (int kc = 0; kc < 4; kc++) {
            const int k0 = kc * 8;
            uint32_t a[2][4];
            #pragma unroll
            for (int mt = 0; mt < 2; mt++) {
                const int r0 = wm * 32 + mt * 16 + gq;
                float v0 = As[(k0 + tig) * A_STR + r0];
                float v1 = As[(k0 + tig) * A_STR + r0 + 8];
                float v2 = As[(k0 + tig + 4) * A_STR + r0];
                float v3 = As[(k0 + tig + 4) * A_STR + r0 + 8];
                if (DOCVT) {
                    a[mt][0] = rna_tf32(v0); a[mt][1] = rna_tf32(v1);
                    a[mt][2] = rna_tf32(v2); a[mt][3] = rna_tf32(v3);
                } else {
                    a[mt][0] = __float_as_uint(v0); a[mt][1] = __float_as_uint(v1);
                    a[mt][2] = __float_as_uint(v2); a[mt][3] = __float_as_uint(v3);
                }
            }
            #pragma unroll
            for (int nt = 0; nt < 4; nt++) {
                const int c0 = wn * 32 + nt * 8 + gq;
                uint32_t b[2];
                b[0] = __float_as_uint(Bs[c0 * B_STR + k0 + tig]);
                b[1] = __float_as_uint(Bs[c0 * B_STR + k0 + tig + 4]);
                mma8(acc[0][nt], a[0], b);
                mma8(acc[1][nt], a[1], b);
            }
        }
    }
    __syncthreads();                       // all mma done
}

// zprep tile compute + scatter store (verbatim from round-11 zprep_kernel body)
__device__ __forceinline__ void zprep_tile(
    float* smf, uint32_t sb, const float* xs, float* zwr,
    int j, int n0, int tid, int wm, int wn, int gq, int tig) {
    float acc[2][4][4];
    #pragma unroll
    for (int a0 = 0; a0 < 2; a0++)
        #pragma unroll
        for (int a1 = 0; a1 < 4; a1++)
            #pragma unroll
            for (int a2 = 0; a2 < 4; a2++) acc[a0][a1][a2] = 0.0f;

    gemm_mainloop<true, false>(acc, smf, sb, xs, g_Wih, nullptr,
                               j, n0, tid, wm, wn, gq, tig);

    const size_t zbase = (size_t)(j * 64) * NB + n0;
    #pragma unroll
    for (int mt = 0; mt < 2; mt++) {
        const int r0 = wm * 32 + mt * 16 + gq;
        #pragma unroll
        for (int nt = 0; nt < 4; nt++) {
            const int c0 = wn * 32 + nt * 8 + 2 * tig;
            zwr[zbase + (size_t)(c0    ) * NB + r0    ] = acc[mt][nt][0];
            zwr[zbase + (size_t)(c0 + 1) * NB + r0    ] = acc[mt][nt][1];
            zwr[zbase + (size_t)(c0    ) * NB + r0 + 8] = acc[mt][nt][2];
            zwr[zbase + (size_t)(c0 + 1) * NB + r0 + 8] = acc[mt][nt][3];
        }
    }
}

// ---------------------------------------------------------------------------
// prologue: seed Z slot 0 with x_0 @ W_ih^T
// ---------------------------------------------------------------------------
__global__ void __launch_bounds__(256, 2)
zprep0_kernel(const float* __restrict__ img, float* __restrict__ zwr) {
    extern __shared__ float smf[];
    const uint32_t sb = smem_u32(smf);
    const int tid = threadIdx.x, lane = tid & 31, wid = tid >> 5;
    const int gq = lane >> 2, tig = lane & 3;
    const int wm = wid >> 1, wn = wid & 1;
    zprep_tile(smf, sb, img, zwr, blockIdx.x, blockIdx.y * 128,
               tid, wm, wn, gq, tig);
}

// ---------------------------------------------------------------------------
// shared epilogue: Z add (optional), shuffle cell update, writebacks
// ---------------------------------------------------------------------------
template <bool HASZ>
__device__ __forceinline__ void step_epilogue(
    float acc[2][4][4], float* smf,
    float* hnext, float* out, int t_out, int TOUT,
    int j, int n0, int tid, int lane, int wid, int wm, int wn, int gq, int tig) {

    if (HASZ) {
        const float* Zs = smf + OFF_Z;
        #pragma unroll
        for (int mt = 0; mt < 2; mt++) {
            const int r0 = wm * 32 + mt * 16 + gq;
            #pragma unroll
            for (int nt = 0; nt < 4; nt++) {
                const int c0 = wn * 32 + nt * 8 + 2 * tig;
                acc[mt][nt][0] += Zs[(c0    ) * Z_STR + r0    ];
                acc[mt][nt][1] += Zs[(c0 + 1) * Z_STR + r0    ];
                acc[mt][nt][2] += Zs[(c0    ) * Z_STR + r0 + 8];
                acc[mt][nt][3] += Zs[(c0 + 1) * Z_STR + r0 + 8];
            }
        }
    }

    float* H2 = smf + OFF_A;            // 16 units x H_STR (aliases A bufs)
    const int mymt = tig & 1;
    const int r0e = wm * 32 + mymt * 16 + gq;
    #pragma unroll
    for (int nt = 0; nt < 4; nt++) {
        const int u = wn * 8 + nt * 2 + (tig >> 1);
        float oth[4];
        #pragma unroll
        for (int e = 0; e < 4; e++)
            oth[e] = __shfl_xor_sync(0xffffffffu, acc[mymt ^ 1][nt][e], 1);
        const float b0 = smf[OFF_BIAS + 4 * u + 0];
        const float b1 = smf[OFF_BIAS + 4 * u + 1];
        const float b2 = smf[OFF_BIAS + 4 * u + 2];
        const float b3 = smf[OFF_BIAS + 4 * u + 3];
        #pragma unroll
        for (int e2 = 0; e2 < 2; e2++) {
            const float ow0 = acc[mymt][nt][2 * e2], ow1 = acc[mymt][nt][2 * e2 + 1];
            const float ot0 = oth[2 * e2],           ot1 = oth[2 * e2 + 1];
            float gi, gf, gg, go;
            if (mymt == 0) { gi = ow0; gf = ow1; gg = ot0; go = ot1; }
            else           { gg = ow0; go = ow1; gi = ot0; gf = ot1; }
            gi += b0; gf += b1; gg += b2; go += b3;
            const int row = r0e + 8 * e2;
            const size_t ci = (size_t)(j * 16 + u) * NB + n0 + row;
            const float cold = g_Cbuf[ci];
            const float cn = sigf(gf) * cold + sigf(gi) * tanhf_(gg);
            g_Cbuf[ci] = cn;
            H2[u * H_STR + row] = sigf(go) * tanhf_(cn);
        }
    }
    __syncthreads();

    #pragma unroll
    for (int q = 0; q < 2; q++) {
        const int u = wid * 2 + q;
        #pragma unroll
        for (int mk = 0; mk < 4; mk++) {
            const int m = mk * 32 + lane;
            hnext[(size_t)(j * 16 + u) * NB + n0 + m] =
                __uint_as_float(rna_tf32(H2[u * H_STR + m]));
        }
    }
    const int hh = lane & 15, rp = lane >> 4;
    #pragma unroll
    for (int i2 = 0; i2 < 8; i2++) {
        const int mr = wid * 16 + i2 * 2 + rp;
        out[(size_t)(n0 + mr) * TOUT * HD + (size_t)t_out * HD + j * 16 + hh] =
            H2[hh * H_STR + mr];
    }
}

// ---------------------------------------------------------------------------
// phase-1 kernel: step t (Z[t&1] L2-hot) + zprep for t+1 into Z[(t+1)&1]
// ---------------------------------------------------------------------------
__global__ void __launch_bounds__(256, 2)
lstm_step_p1(const float* __restrict__ zrd,      // Z slot for step t
             float* __restrict__ zwr,            // Z slot for step t+1
             const float* __restrict__ imgnext,  // img[t+1] slice or null
             const float* __restrict__ hprev,
             float* __restrict__ hnext,
             float* __restrict__ out, int t_out, int TOUT) {
    extern __shared__ float smf[];
    const uint32_t sb = smem_u32(smf);
    const int tid = threadIdx.x, lane = tid & 31, wid = tid >> 5;
    const int gq = lane >> 2, tig = lane & 3;
    const int wm = wid >> 1, wn = wid & 1;
    const int j = blockIdx.x, n0 = blockIdx.y * 128;

    if (tid < 64) smf[OFF_BIAS + tid] = g_bias[j * 64 + tid];

    // ---- half 1: recurrent step (dependent chain) ----
    float acc[2][4][4];
    #pragma unroll
    for (int a0 = 0; a0 < 2; a0++)
        #pragma unroll
        for (int a1 = 0; a1 < 4; a1++)
            #pragma unroll
            for (int a2 = 0; a2 < 4; a2++) acc[a0][a1][a2] = 0.0f;

    gemm_mainloop<false, true>(acc, smf, sb, hprev, g_Whh,
                               zrd + (size_t)(j * 64) * NB + n0,
                               j, n0, tid, wm, wn, gq, tig);
    step_epilogue<true>(acc, smf, hnext, out, t_out, TOUT,
                        j, n0, tid, lane, wid, wm, wn, gq, tig);
    __syncthreads();       // H2 (A bufs) fully consumed before zprep reuses

    // ---- half 2: zprep for t+1 (independent; fills cross-CTA slack) ----
    if (imgnext != nullptr)
        zprep_tile(smf, sb, imgnext, zwr, j, n0, tid, wm, wn, gq, tig);
}

// ---------------------------------------------------------------------------
// phase-2 kernel: gates = h @ Wsum^T + b (no Z)
// ---------------------------------------------------------------------------
__global__ void __launch_bounds__(256, 2)
lstm_step_p2(const float* __restrict__ hprev, float* __restrict__ hnext,
             float* __restrict__ out, int t_out, int TOUT) {
    extern __shared__ float smf[];
    const uint32_t sb = smem_u32(smf);
    const int tid = threadIdx.x, lane = tid & 31, wid = tid >> 5;
    const int gq = lane >> 2, tig = lane & 3;
    const int wm = wid >> 1, wn = wid & 1;
    const int j = blockIdx.x, n0 = blockIdx.y * 128;

    if (tid < 64) smf[OFF_BIAS + tid] = g_bias[j * 64 + tid];

    float acc[2][4][4];
    #pragma unroll
    for (int a0 = 0; a0 < 2; a0++)
        #pragma unroll
        for (int a1 = 0; a1 < 4; a1++)
            #pragma unroll
            for (int a2 = 0; a2 < 4; a2++) acc[a0][a1][a2] = 0.0f;

    gemm_mainloop<false, false>(acc, smf, sb, hprev, g_Wsum, nullptr,
                                j, n0, tid, wm, wn, gq, tig);
    step_epilogue<false>(acc, smf, hnext, out, t_out, TOUT,
                         j, n0, tid, lane, wid, wm, wn, gq, tig);
}

// ---------------------------------------------------------------------------
// launch: prep + zprep0 + 60 fused (step+zprep) + 54 plain steps
// ---------------------------------------------------------------------------
extern "C" void kernel_launch(void* const* d_in, const int* in_sizes, int n_in,
                              void* d_out, int out_size) {
    const float* img = (const float*)d_in[0];
    const float* Wih = (const float*)d_in[2];
    const float* Whh = (const float*)d_in[3];
    const float* bih = (const float*)d_in[4];
    const float* bhh = (const float*)d_in[5];
    float* out = (float*)d_out;

    const int T    = in_sizes[0] / (HD * NB);       // 60
    const int TOUT = out_size / (NB * HD);          // 114

    void *h0p, *h1p, *zp;
    cudaGetSymbolAddress(&h0p, g_Hbuf0);
    cudaGetSymbolAddress(&h1p, g_Hbuf1);
    cudaGetSymbolAddress(&zp, g_Z);
    float* hb[2] = {(float*)h0p, (float*)h1p};
    float* zs = (float*)zp;                         // 2 slots of NG*NB

    cudaFuncSetAttribute((const void*)zprep0_kernel,
                         cudaFuncAttributeMaxDynamicSharedMemorySize, SM_BYTES);
    cudaFuncSetAttribute((const void*)lstm_step_p1,
                         cudaFuncAttributeMaxDynamicSharedMemorySize, SM_BYTES);
    cudaFuncSetAttribute((const void*)lstm_step_p2,
                         cudaFuncAttributeMaxDynamicSharedMemorySize, SM_BYTES);

    prep_kernel<<<256, 256>>>(Wih, Whh, bih, bhh);

    dim3 grid(8, NB / 128);                         // 256 CTAs, 2/SM
    zprep0_kernel<<<grid, 256, SM_BYTES>>>(img, zs);   // Z slot 0 = t0

    for (int t = 0; t < TOUT; t++) {
        float* hp = hb[t & 1];
        float* hn = hb[(t + 1) & 1];
        if (t < T) {
            const float* nxt = (t + 1 < T) ? img + (size_t)(t + 1) * HD * NB
                                           : nullptr;
            lstm_step_p1<<<grid, 256, SM_BYTES>>>(
                zs + (size_t)(t & 1) * NG * NB,
                zs + (size_t)((t + 1) & 1) * NG * NB,
                nxt, hp, hn, out, t, TOUT);
        } else {
            lstm_step_p2<<<grid, 256, SM_BYTES>>>(hp, hn, out, t, TOUT);
        }
    }
}

// round 15
// speedup vs baseline: 1.4745x; 1.0042x over previous
#include <cuda_runtime.h>
#include <cstdint>

// ============================================================================
// LSTM_34883724378521 : T=60, C=H=128, N=4096, TOUT=114
// Phase-1 kernel per step t (grid 8x32, 256 thr, 2 CTAs/SM):
//   half (a): acc := Z[t&1] (32 LDGs straight into accumulator registers,
//             L2-hot ring slot written by the previous kernel), then
//             acc += h @ W_hh^T (4x K=32 cp.async-pipelined chunks),
//             epilogue (bias, shuffle cell update, writebacks).
//   half (b): Z[(t+1)&1] = img[t+1] @ W_ih^T  (independent; fills slack).
// Phase-2: gates = h @ (W_ih+W_hh)^T + b  (proven ~3us step).
// Z never touches cp.async groups -> no forced drain on the chunk waits.
// ============================================================================
#define NB 4096
#define HD 128
#define NG 512

__device__ __forceinline__ uint32_t smem_u32(const void* p) {
    uint32_t a;
    asm("{ .reg .u64 t; cvta.to.shared.u64 t, %1; cvt.u32.u64 %0, t; }"
        : "=r"(a) : "l"(p));
    return a;
}
__device__ __forceinline__ void cp16(uint32_t dst, const void* src) {
    asm volatile("cp.async.cg.shared.global [%0], [%1], 16;" :: "r"(dst), "l"(src));
}
#define CP_COMMIT() asm volatile("cp.async.commit_group;" ::: "memory")
#define CP_WAIT(n)  asm volatile("cp.async.wait_group %0;" :: "n"(n) : "memory")

__device__ __forceinline__ uint32_t rna_tf32(float v) {
    uint32_t u; asm("cvt.rna.tf32.f32 %0, %1;" : "=r"(u) : "f"(v)); return u;
}
__device__ __forceinline__ void mma8(float* d, const uint32_t* a, const uint32_t* b) {
    asm volatile(
        "mma.sync.aligned.m16n8k8.row.col.f32.tf32.tf32.f32 "
        "{%0,%1,%2,%3}, {%4,%5,%6,%7}, {%8,%9}, {%0,%1,%2,%3};"
        : "+f"(d[0]), "+f"(d[1]), "+f"(d[2]), "+f"(d[3])
        : "r"(a[0]), "r"(a[1]), "r"(a[2]), "r"(a[3]), "r"(b[0]), "r"(b[1]));
}
__device__ __forceinline__ float sigf(float x)   { return 1.0f / (1.0f + __expf(-x)); }
__device__ __forceinline__ float tanhf_(float x) { return 1.0f - 2.0f / (__expf(2.0f * x) + 1.0f); }

// ---------------------------------------------------------------------------
// persistent device state
// ---------------------------------------------------------------------------
__device__ float g_Hbuf0[HD * NB];     // h state, h-major [H][N] (tf32-rounded)
__device__ float g_Hbuf1[HD * NB];
__device__ float g_Cbuf [HD * NB];     // c state, h-major
__device__ float g_Whh[NG * HD];       // permuted W_hh, tf32-rounded
__device__ float g_Wih[NG * HD];       // permuted W_ih, tf32-rounded
__device__ float g_Wsum[NG * HD];      // permuted W_ih+W_hh, tf32-rounded
__device__ float g_bias[NG];           // permuted b_ih + b_hh
__device__ float g_Z[2 * NG * NB];     // 16.8 MB ring: x@W_ih^T, 2 slots

// ---------------------------------------------------------------------------
// prep: row perm r = 4*h+g <- g*128+h ; RNA-round weights; zero state
// ---------------------------------------------------------------------------
__global__ void prep_kernel(const float* __restrict__ Wih, const float* __restrict__ Whh,
                            const float* __restrict__ bih, const float* __restrict__ bhh) {
    int tid = blockIdx.x * 256 + threadIdx.x;       // 256*256 = 65536
    int r = tid >> 7, k = tid & 127;
    int h = r >> 2, g = r & 3;
    int orig = g * HD + h;
    float wi = Wih[orig * HD + k], wh = Whh[orig * HD + k];
    g_Wih [r * HD + k] = __uint_as_float(rna_tf32(wi));
    g_Whh [r * HD + k] = __uint_as_float(rna_tf32(wh));
    g_Wsum[r * HD + k] = __uint_as_float(rna_tf32(wi + wh));
    if (k == 0) g_bias[r] = bih[orig] + bhh[orig];
    for (int i = tid; i < HD * NB; i += 65536) {
        g_Hbuf0[i] = 0.0f;
        g_Cbuf[i]  = 0.0f;
    }
}

// ---------------------------------------------------------------------------
// smem layout (float offsets): bias(64) | 2x A(32x136) | 2x B(64x36)
// H2 stage (16 x 130) aliases A buffer 0 after the step mainloop.
// ---------------------------------------------------------------------------
static constexpr int A_STR = 136, B_STR = 36, H_STR = 130;
static constexpr int A_FL  = 32 * A_STR;      // 4352
static constexpr int B_FL  = 64 * B_STR;      // 2304
static constexpr int OFF_BIAS = 0;
static constexpr int OFF_A    = 64;
static constexpr int OFF_B    = OFF_A + 2 * A_FL;     // 8768
static constexpr int SM_FLOATS = OFF_B + 2 * B_FL;    // 13376
static constexpr int SM_BYTES  = SM_FLOATS * 4;       // 53504 -> 2 CTAs/SM

// ---------------------------------------------------------------------------
// shared mainloop: 4 chunks of K=32, 2 A bufs / 2 B bufs, prefetch dist 1.
// Accumulates ONTO caller-initialized acc (Z-init or zero).
// ---------------------------------------------------------------------------
template <bool DOCVT>
__device__ __forceinline__ void gemm_mainloop(
    float acc[2][4][4], float* smf, uint32_t sb,
    const float* asrc, const float* W,
    int j, int n0, int tid, int wm, int wn, int gq, int tig) {

    auto loadC = [&](int ch) {
        const int buf = ch & 1;
        const uint32_t ab = sb + (uint32_t)(OFF_A + buf * A_FL) * 4;
        const uint32_t bb = sb + (uint32_t)(OFF_B + buf * B_FL) * 4;
        #pragma unroll
        for (int it = 0; it < 4; it++) {   // A: 32 k-rows x 128 m
            int idx = tid + it * 256;
            int kk = idx >> 5, mp = (idx & 31) << 2;
            cp16(ab + (uint32_t)(kk * A_STR + mp) * 4,
                 asrc + (size_t)(ch * 32 + kk) * NB + n0 + mp);
        }
        #pragma unroll
        for (int it = 0; it < 2; it++) {   // B: 64 gate-cols x 32 k
            int idx = tid + it * 256;
            int n = idx >> 3, q = (idx & 7) << 2;
            cp16(bb + (uint32_t)(n * B_STR + q) * 4,
                 W + (size_t)(j * 64 + n) * HD + ch * 32 + q);
        }
        CP_COMMIT();
    };

    loadC(0);
    #pragma unroll
    for (int ch = 0; ch < 4; ch++) {
        CP_WAIT(0);
        __syncthreads();                   // chunk ch ready; mma(ch-1) done
        if (ch + 1 < 4) loadC(ch + 1);     // writes buf (ch+1)&1 (drained)
        const float* As = smf + OFF_A + (ch & 1) * A_FL;
        const float* Bs = smf + OFF_B + (ch & 1) * B_FL;

        #pragma unroll
        for (int kc = 0; kc < 4; kc++) {
            const int k0 = kc * 8;
            uint32_t a[2][4];
            #pragma unroll
            for (int mt = 0; mt < 2; mt++) {
                const int r0 = wm * 32 + mt * 16 + gq;
                float v0 = As[(k0 + tig) * A_STR + r0];
                float v1 = As[(k0 + tig) * A_STR + r0 + 8];
                float v2 = As[(k0 + tig + 4) * A_STR + r0];
                float v3 = As[(k0 + tig + 4) * A_STR + r0 + 8];
                if (DOCVT) {
                    a[mt][0] = rna_tf32(v0); a[mt][1] = rna_tf32(v1);
                    a[mt][2] = rna_tf32(v2); a[mt][3] = rna_tf32(v3);
                } else {
                    a[mt][0] = __float_as_uint(v0); a[mt][1] = __float_as_uint(v1);
                    a[mt][2] = __float_as_uint(v2); a[mt][3] = __float_as_uint(v3);
                }
            }
            #pragma unroll
            for (int nt = 0; nt < 4; nt++) {
                const int c0 = wn * 32 + nt * 8 + gq;
                uint32_t b[2];
                b[0] = __float_as_uint(Bs[c0 * B_STR + k0 + tig]);
                b[1] = __float_as_uint(Bs[c0 * B_STR + k0 + tig + 4]);
                mma8(acc[0][nt], a[0], b);
                mma8(acc[1][nt], a[1], b);
            }
        }
    }
    __syncthreads();                       // all mma done
}

// zprep tile compute + scatter store: Z = x @ W_ih^T (acc zero-init inside)
__device__ __forceinline__ void zprep_tile(
    float* smf, uint32_t sb, const float* xs, float* zwr,
    int j, int n0, int tid, int wm, int wn, int gq, int tig) {
    float acc[2][4][4];
    #pragma unroll
    for (int a0 = 0; a0 < 2; a0++)
        #pragma unroll
        for (int a1 = 0; a1 < 4; a1++)
            #pragma unroll
            for (int a2 = 0; a2 < 4; a2++) acc[a0][a1][a2] = 0.0f;

    gemm_mainloop<true>(acc, smf, sb, xs, g_Wih, j, n0, tid, wm, wn, gq, tig);

    const size_t zbase = (size_t)(j * 64) * NB + n0;
    #pragma unroll
    for (int mt = 0; mt < 2; mt++) {
        const int r0 = wm * 32 + mt * 16 + gq;
        #pragma unroll
        for (int nt = 0; nt < 4; nt++) {
            const int c0 = wn * 32 + nt * 8 + 2 * tig;
            zwr[zbase + (size_t)(c0    ) * NB + r0    ] = acc[mt][nt][0];
            zwr[zbase + (size_t)(c0 + 1) * NB + r0    ] = acc[mt][nt][1];
            zwr[zbase + (size_t)(c0    ) * NB + r0 + 8] = acc[mt][nt][2];
            zwr[zbase + (size_t)(c0 + 1) * NB + r0 + 8] = acc[mt][nt][3];
        }
    }
}

// prologue: seed Z slot 0 with x_0 @ W_ih^T
__global__ void __launch_bounds__(256, 2)
zprep0_kernel(const float* __restrict__ img, float* __restrict__ zwr) {
    extern __shared__ float smf[];
    const uint32_t sb = smem_u32(smf);
    const int tid = threadIdx.x, lane = tid & 31, wid = tid >> 5;
    const int gq = lane >> 2, tig = lane & 3;
    const int wm = wid >> 1, wn = wid & 1;
    zprep_tile(smf, sb, img, zwr, blockIdx.x, blockIdx.y * 128,
               tid, wm, wn, gq, tig);
}

// ---------------------------------------------------------------------------
// shared epilogue: shuffle cell update + writebacks (acc already holds gates)
// ---------------------------------------------------------------------------
__device__ __forceinline__ void step_epilogue(
    float acc[2][4][4], float* smf,
    float* hnext, float* out, int t_out, int TOUT,
    int j, int n0, int tid, int lane, int wid, int wm, int wn, int gq, int tig) {

    float* H2 = smf + OFF_A;            // 16 units x H_STR (aliases A bufs)
    const int mymt = tig & 1;
    const int r0e = wm * 32 + mymt * 16 + gq;
    #pragma unroll
    for (int nt = 0; nt < 4; nt++) {
        const int u = wn * 8 + nt * 2 + (tig >> 1);
        float oth[4];
        #pragma unroll
        for (int e = 0; e < 4; e++)
            oth[e] = __shfl_xor_sync(0xffffffffu, acc[mymt ^ 1][nt][e], 1);
        const float b0 = smf[OFF_BIAS + 4 * u + 0];
        const float b1 = smf[OFF_BIAS + 4 * u + 1];
        const float b2 = smf[OFF_BIAS + 4 * u + 2];
        const float b3 = smf[OFF_BIAS + 4 * u + 3];
        #pragma unroll
        for (int e2 = 0; e2 < 2; e2++) {
            const float ow0 = acc[mymt][nt][2 * e2], ow1 = acc[mymt][nt][2 * e2 + 1];
            const float ot0 = oth[2 * e2],           ot1 = oth[2 * e2 + 1];
            float gi, gf, gg, go;
            if (mymt == 0) { gi = ow0; gf = ow1; gg = ot0; go = ot1; }
            else           { gg = ow0; go = ow1; gi = ot0; gf = ot1; }
            gi += b0; gf += b1; gg += b2; go += b3;
            const int row = r0e + 8 * e2;
            const size_t ci = (size_t)(j * 16 + u) * NB + n0 + row;
            const float cold = g_Cbuf[ci];
            const float cn = sigf(gf) * cold + sigf(gi) * tanhf_(gg);
            g_Cbuf[ci] = cn;
            H2[u * H_STR + row] = sigf(go) * tanhf_(cn);
        }
    }
    __syncthreads();

    #pragma unroll
    for (int q = 0; q < 2; q++) {
        const int u = wid * 2 + q;
        #pragma unroll
        for (int mk = 0; mk < 4; mk++) {
            const int m = mk * 32 + lane;
            hnext[(size_t)(j * 16 + u) * NB + n0 + m] =
                __uint_as_float(rna_tf32(H2[u * H_STR + m]));
        }
    }
    const int hh = lane & 15, rp = lane >> 4;
    #pragma unroll
    for (int i2 = 0; i2 < 8; i2++) {
        const int mr = wid * 16 + i2 * 2 + rp;
        out[(size_t)(n0 + mr) * TOUT * HD + (size_t)t_out * HD + j * 16 + hh] =
            H2[hh * H_STR + mr];
    }
}

// ---------------------------------------------------------------------------
// phase-1 kernel: acc := Z[t&1] (LDG-to-registers), acc += h@Whh, epilogue;
// then zprep img[t+1] into Z[(t+1)&1].
// ---------------------------------------------------------------------------
__global__ void __launch_bounds__(256, 2)
lstm_step_p1(const float* __restrict__ zrd,      // Z slot for step t
             float* __restrict__ zwr,            // Z slot for step t+1
             const float* __restrict__ imgnext,  // img[t+1] slice or null
             const float* __restrict__ hprev,
             float* __restrict__ hnext,
             float* __restrict__ out, int t_out, int TOUT) {
    extern __shared__ float smf[];
    const uint32_t sb = smem_u32(smf);
    const int tid = threadIdx.x, lane = tid & 31, wid = tid >> 5;
    const int gq = lane >> 2, tig = lane & 3;
    const int wm = wid >> 1, wn = wid & 1;
    const int j = blockIdx.x, n0 = blockIdx.y * 128;

    if (tid < 64) smf[OFF_BIAS + tid] = g_bias[j * 64 + tid];

    // ---- acc := Z (32 plain LDGs into accumulator registers; L2-hot ring) --
    float acc[2][4][4];
    {
        const float* zb = zrd + (size_t)(j * 64) * NB + n0;
        #pragma unroll
        for (int mt = 0; mt < 2; mt++) {
            const int r0 = wm * 32 + mt * 16 + gq;
            #pragma unroll
            for (int nt = 0; nt < 4; nt++) {
                const int c0 = wn * 32 + nt * 8 + 2 * tig;
                acc[mt][nt][0] = zb[(size_t)(c0    ) * NB + r0    ];
                acc[mt][nt][1] = zb[(size_t)(c0 + 1) * NB + r0    ];
                acc[mt][nt][2] = zb[(size_t)(c0    ) * NB + r0 + 8];
                acc[mt][nt][3] = zb[(size_t)(c0 + 1) * NB + r0 + 8];
            }
        }
    }

    // ---- acc += h @ W_hh^T ----
    gemm_mainloop<false>(acc, smf, sb, hprev, g_Whh, j, n0, tid, wm, wn, gq, tig);
    step_epilogue(acc, smf, hnext, out, t_out, TOUT,
                  j, n0, tid, lane, wid, wm, wn, gq, tig);
    __syncthreads();       // H2 (A bufs) fully consumed before zprep reuses

    // ---- zprep for t+1 (independent; fills cross-CTA slack) ----
    if (imgnext != nullptr)
        zprep_tile(smf, sb, imgnext, zwr, j, n0, tid, wm, wn, gq, tig);
}

// ---------------------------------------------------------------------------
// phase-2 kernel: gates = h @ Wsum^T + b
// ---------------------------------------------------------------------------
__global__ void __launch_bounds__(256, 2)
lstm_step_p2(const float* __restrict__ hprev, float* __restrict__ hnext,
             float* __restrict__ out, int t_out, int TOUT) {
    extern __shared__ float smf[];
    const uint32_t sb = smem_u32(smf);
    const int tid = threadIdx.x, lane = tid & 31, wid = tid >> 5;
    const int gq = lane >> 2, tig = lane & 3;
    const int wm = wid >> 1, wn = wid & 1;
    const int j = blockIdx.x, n0 = blockIdx.y * 128;

    if (tid < 64) smf[OFF_BIAS + tid] = g_bias[j * 64 + tid];

    float acc[2][4][4];
    #pragma unroll
    for (int a0 = 0; a0 < 2; a0++)
        #pragma unroll
        for (int a1 = 0; a1 < 4; a1++)
            #pragma unroll
            for (int a2 = 0; a2 < 4; a2++) acc[a0][a1][a2] = 0.0f;

    gemm_mainloop<false>(acc, smf, sb, hprev, g_Wsum, j, n0, tid, wm, wn, gq, tig);
    step_epilogue(acc, smf, hnext, out, t_out, TOUT,
                  j, n0, tid, lane, wid, wm, wn, gq, tig);
}

// ---------------------------------------------------------------------------
// launch: prep + zprep0 + 60 fused (step+zprep) + 54 plain steps
// ---------------------------------------------------------------------------
extern "C" void kernel_launch(void* const* d_in, const int* in_sizes, int n_in,
                              void* d_out, int out_size) {
    const float* img = (const float*)d_in[0];
    const float* Wih = (const float*)d_in[2];
    const float* Whh = (const float*)d_in[3];
    const float* bih = (const float*)d_in[4];
    const float* bhh = (const float*)d_in[5];
    float* out = (float*)d_out;

    const int T    = in_sizes[0] / (HD * NB);       // 60
    const int TOUT = out_size / (NB * HD);          // 114

    void *h0p, *h1p, *zp;
    cudaGetSymbolAddress(&h0p, g_Hbuf0);
    cudaGetSymbolAddress(&h1p, g_Hbuf1);
    cudaGetSymbolAddress(&zp, g_Z);
    float* hb[2] = {(float*)h0p, (float*)h1p};
    float* zs = (float*)zp;                         // 2 slots of NG*NB

    cudaFuncSetAttribute((const void*)zprep0_kernel,
                         cudaFuncAttributeMaxDynamicSharedMemorySize, SM_BYTES);
    cudaFuncSetAttribute((const void*)lstm_step_p1,
                         cudaFuncAttributeMaxDynamicSharedMemorySize, SM_BYTES);
    cudaFuncSetAttribute((const void*)lstm_step_p2,
                         cudaFuncAttributeMaxDynamicSharedMemorySize, SM_BYTES);

    prep_kernel<<<256, 256>>>(Wih, Whh, bih, bhh);

    dim3 grid(8, NB / 128);                         // 256 CTAs, 2/SM
    zprep0_kernel<<<grid, 256, SM_BYTES>>>(img, zs);   // Z slot 0 = t0

    for (int t = 0; t < TOUT; t++) {
        float* hp = hb[t & 1];
        float* hn = hb[(t + 1) & 1];
        if (t < T) {
            const float* nxt = (t + 1 < T) ? img + (size_t)(t + 1) * HD * NB
                                           : nullptr;
            lstm_step_p1<<<grid, 256, SM_BYTES>>>(
                zs + (size_t)(t & 1) * NG * NB,
                zs + (size_t)((t + 1) & 1) * NG * NB,
                nxt, hp, hn, out, t, TOUT);
        } else {
            lstm_step_p2<<<grid, 256, SM_BYTES>>>(hp, hn, out, t, TOUT);
        }
    }
}

// round 16
// speedup vs baseline: 1.5012x; 1.0181x over previous
#include <cuda_runtime.h>
#include <cstdint>

// ============================================================================
// LSTM_34883724378521 : T=60, C=H=128, N=4096, TOUT=114
// Phase-1 kernel per step t (grid 8x32, 256 thr, 2 CTAs/SM):
//   half (a): acc := Z[t&1] (LDGs into accumulator regs; ring slot written by
//             the PREVIOUS kernel -> genuinely L2-hot), acc += h @ W_hh^T
//             (2-buf cp.async pipeline; h is L2-hot), epilogue.
//   half (b): Z[(t+1)&1] = img[t+1] @ W_ih^T with a 4-buffer FULLY-PREFETCHED
//             pipeline (all chunk loads in flight -> cold-DRAM img read is
//             bandwidth-streamed, not latency-serialized).
// Phase-2: gates = h @ (W_ih+W_hh)^T + b  (L2-hot, ~3us).
// ============================================================================
#define NB 4096
#define HD 128
#define NG 512

__device__ __forceinline__ uint32_t smem_u32(const void* p) {
    uint32_t a;
    asm("{ .reg .u64 t; cvta.to.shared.u64 t, %1; cvt.u32.u64 %0, t; }"
        : "=r"(a) : "l"(p));
    return a;
}
__device__ __forceinline__ void cp16(uint32_t dst, const void* src) {
    asm volatile("cp.async.cg.shared.global [%0], [%1], 16;" :: "r"(dst), "l"(src));
}
#define CP_COMMIT() asm volatile("cp.async.commit_group;" ::: "memory")
#define CP_WAIT(n)  asm volatile("cp.async.wait_group %0;" :: "n"(n) : "memory")

__device__ __forceinline__ uint32_t rna_tf32(float v) {
    uint32_t u; asm("cvt.rna.tf32.f32 %0, %1;" : "=r"(u) : "f"(v)); return u;
}
__device__ __forceinline__ void mma8(float* d, const uint32_t* a, const uint32_t* b) {
    asm volatile(
        "mma.sync.aligned.m16n8k8.row.col.f32.tf32.tf32.f32 "
        "{%0,%1,%2,%3}, {%4,%5,%6,%7}, {%8,%9}, {%0,%1,%2,%3};"
        : "+f"(d[0]), "+f"(d[1]), "+f"(d[2]), "+f"(d[3])
        : "r"(a[0]), "r"(a[1]), "r"(a[2]), "r"(a[3]), "r"(b[0]), "r"(b[1]));
}
__device__ __forceinline__ float sigf(float x)   { return 1.0f / (1.0f + __expf(-x)); }
__device__ __forceinline__ float tanhf_(float x) { return 1.0f - 2.0f / (__expf(2.0f * x) + 1.0f); }

// ---------------------------------------------------------------------------
// persistent device state
// ---------------------------------------------------------------------------
__device__ float g_Hbuf0[HD * NB];     // h state, h-major [H][N] (tf32-rounded)
__device__ float g_Hbuf1[HD * NB];
__device__ float g_Cbuf [HD * NB];     // c state, h-major
__device__ float g_Whh[NG * HD];       // permuted W_hh, tf32-rounded
__device__ float g_Wih[NG * HD];       // permuted W_ih, tf32-rounded
__device__ float g_Wsum[NG * HD];      // permuted W_ih+W_hh, tf32-rounded
__device__ float g_bias[NG];           // permuted b_ih + b_hh
__device__ float g_Z[2 * NG * NB];     // 16.8 MB ring: x@W_ih^T, 2 slots

// ---------------------------------------------------------------------------
// prep: row perm r = 4*h+g <- g*128+h ; RNA-round weights; zero state
// ---------------------------------------------------------------------------
__global__ void prep_kernel(const float* __restrict__ Wih, const float* __restrict__ Whh,
                            const float* __restrict__ bih, const float* __restrict__ bhh) {
    int tid = blockIdx.x * 256 + threadIdx.x;       // 256*256 = 65536
    int r = tid >> 7, k = tid & 127;
    int h = r >> 2, g = r & 3;
    int orig = g * HD + h;
    float wi = Wih[orig * HD + k], wh = Whh[orig * HD + k];
    g_Wih [r * HD + k] = __uint_as_float(rna_tf32(wi));
    g_Whh [r * HD + k] = __uint_as_float(rna_tf32(wh));
    g_Wsum[r * HD + k] = __uint_as_float(rna_tf32(wi + wh));
    if (k == 0) g_bias[r] = bih[orig] + bhh[orig];
    for (int i = tid; i < HD * NB; i += 65536) {
        g_Hbuf0[i] = 0.0f;
        g_Cbuf[i]  = 0.0f;
    }
}

// ---------------------------------------------------------------------------
// smem layout (float offsets): bias(64) | 4x A(32x136) | 4x B(64x36)
// step half uses A/B bufs 0-1 (2-buf pipeline); zprep half uses bufs 0-3
// (fully prefetched). H2 stage (16x130) aliases A buf 0 after step mainloop.
// ---------------------------------------------------------------------------
static constexpr int A_STR = 136, B_STR = 36, H_STR = 130;
static constexpr int A_FL  = 32 * A_STR;      // 4352
static constexpr int B_FL  = 64 * B_STR;      // 2304
static constexpr int OFF_BIAS = 0;
static constexpr int OFF_A    = 64;
static constexpr int OFF_B    = OFF_A + 4 * A_FL;     // 17472
static constexpr int SM_FLOATS = OFF_B + 4 * B_FL;    // 26688
static constexpr int SM_BYTES  = SM_FLOATS * 4;       // 106752 -> 2 CTAs/SM

// ---------------------------------------------------------------------------
// chunk loader shared by both mainloops
// ---------------------------------------------------------------------------
__device__ __forceinline__ void load_chunk(
    uint32_t sb, int buf, const float* asrc, const float* W,
    int ch, int j, int n0, int tid) {
    const uint32_t ab = sb + (uint32_t)(OFF_A + buf * A_FL) * 4;
    const uint32_t bb = sb + (uint32_t)(OFF_B + buf * B_FL) * 4;
    #pragma unroll
    for (int it = 0; it < 4; it++) {   // A: 32 k-rows x 128 m
        int idx = tid + it * 256;
        int kk = idx >> 5, mp = (idx & 31) << 2;
        cp16(ab + (uint32_t)(kk * A_STR + mp) * 4,
             asrc + (size_t)(ch * 32 + kk) * NB + n0 + mp);
    }
    #pragma unroll
    for (int it = 0; it < 2; it++) {   // B: 64 gate-cols x 32 k
        int idx = tid + it * 256;
        int n = idx >> 3, q = (idx & 7) << 2;
        cp16(bb + (uint32_t)(n * B_STR + q) * 4,
             W + (size_t)(j * 64 + n) * HD + ch * 32 + q);
    }
    CP_COMMIT();
}

// inner MMA for one K=32 chunk from smem bufs
template <bool DOCVT>
__device__ __forceinline__ void chunk_mma(
    float acc[2][4][4], const float* As, const float* Bs,
    int wm, int wn, int gq, int tig) {
    #pragma unroll
    for (int kc = 0; kc < 4; kc++) {
        const int k0 = kc * 8;
        uint32_t a[2][4];
        #pragma unroll
        for (int mt = 0; mt < 2; mt++) {
            const int r0 = wm * 32 + mt * 16 + gq;
            float v0 = As[(k0 + tig) * A_STR + r0];
            float v1 = As[(k0 + tig) * A_STR + r0 + 8];
            float v2 = As[(k0 + tig + 4) * A_STR + r0];
            float v3 = As[(k0 + tig + 4) * A_STR + r0 + 8];
            if (DOCVT) {
                a[mt][0] = rna_tf32(v0); a[mt][1] = rna_tf32(v1);
                a[mt][2] = rna_tf32(v2); a[mt][3] = rna_tf32(v3);
            } else {
                a[mt][0] = __float_as_uint(v0); a[mt][1] = __float_as_uint(v1);
                a[mt][2] = __float_as_uint(v2); a[mt][3] = __float_as_uint(v3);
            }
        }
        #pragma unroll
        for (int nt = 0; nt < 4; nt++) {
            const int c0 = wn * 32 + nt * 8 + gq;
            uint32_t b[2];
            b[0] = __float_as_uint(Bs[c0 * B_STR + k0 + tig]);
            b[1] = __float_as_uint(Bs[c0 * B_STR + k0 + tig + 4]);
            mma8(acc[0][nt], a[0], b);
            mma8(acc[1][nt], a[1], b);
        }
    }
}

// ---------------------------------------------------------------------------
// 2-buffer mainloop (L2-hot operands): identical structure to round-15
// ---------------------------------------------------------------------------
__device__ __forceinline__ void gemm_hot(
    float acc[2][4][4], float* smf, uint32_t sb,
    const float* asrc, const float* W,
    int j, int n0, int tid, int wm, int wn, int gq, int tig) {
    load_chunk(sb, 0, asrc, W, 0, j, n0, tid);
    #pragma unroll
    for (int ch = 0; ch < 4; ch++) {
        CP_WAIT(0);
        __syncthreads();
        if (ch + 1 < 4) load_chunk(sb, (ch + 1) & 1, asrc, W, ch + 1, j, n0, tid);
        chunk_mma<false>(acc, smf + OFF_A + (ch & 1) * A_FL,
                         smf + OFF_B + (ch & 1) * B_FL, wm, wn, gq, tig);
    }
    __syncthreads();
}

// ---------------------------------------------------------------------------
// 4-buffer fully-prefetched mainloop (cold-DRAM img): all loads in flight
// ---------------------------------------------------------------------------
__device__ __forceinline__ void gemm_deep_cvt(
    float acc[2][4][4], float* smf, uint32_t sb,
    const float* asrc, const float* W,
    int j, int n0, int tid, int wm, int wn, int gq, int tig) {
    load_chunk(sb, 0, asrc, W, 0, j, n0, tid);
    load_chunk(sb, 1, asrc, W, 1, j, n0, tid);
    load_chunk(sb, 2, asrc, W, 2, j, n0, tid);
    load_chunk(sb, 3, asrc, W, 3, j, n0, tid);
    CP_WAIT(3); __syncthreads();
    chunk_mma<true>(acc, smf + OFF_A + 0 * A_FL, smf + OFF_B + 0 * B_FL, wm, wn, gq, tig);
    CP_WAIT(2); __syncthreads();
    chunk_mma<true>(acc, smf + OFF_A + 1 * A_FL, smf + OFF_B + 1 * B_FL, wm, wn, gq, tig);
    CP_WAIT(1); __syncthreads();
    chunk_mma<true>(acc, smf + OFF_A + 2 * A_FL, smf + OFF_B + 2 * B_FL, wm, wn, gq, tig);
    CP_WAIT(0); __syncthreads();
    chunk_mma<true>(acc, smf + OFF_A + 3 * A_FL, smf + OFF_B + 3 * B_FL, wm, wn, gq, tig);
    __syncthreads();
}

// zprep tile: Z = x @ W_ih^T (deep pipeline) + coalesced scatter store
__device__ __forceinline__ void zprep_tile(
    float* smf, uint32_t sb, const float* xs, float* zwr,
    int j, int n0, int tid, int wm, int wn, int gq, int tig) {
    float acc[2][4][4];
    #pragma unroll
    for (int a0 = 0; a0 < 2; a0++)
        #pragma unroll
        for (int a1 = 0; a1 < 4; a1++)
            #pragma unroll
            for (int a2 = 0; a2 < 4; a2++) acc[a0][a1][a2] = 0.0f;

    gemm_deep_cvt(acc, smf, sb, xs, g_Wih, j, n0, tid, wm, wn, gq, tig);

    const size_t zbase = (size_t)(j * 64) * NB + n0;
    #pragma unroll
    for (int mt = 0; mt < 2; mt++) {
        const int r0 = wm * 32 + mt * 16 + gq;
        #pragma unroll
        for (int nt = 0; nt < 4; nt++) {
            const int c0 = wn * 32 + nt * 8 + 2 * tig;
            zwr[zbase + (size_t)(c0    ) * NB + r0    ] = acc[mt][nt][0];
            zwr[zbase + (size_t)(c0 + 1) * NB + r0    ] = acc[mt][nt][1];
            zwr[zbase + (size_t)(c0    ) * NB + r0 + 8] = acc[mt][nt][2];
            zwr[zbase + (size_t)(c0 + 1) * NB + r0 + 8] = acc[mt][nt][3];
        }
    }
}

// prologue: seed Z slot 0 with x_0 @ W_ih^T
__global__ void __launch_bounds__(256, 2)
zprep0_kernel(const float* __restrict__ img, float* __restrict__ zwr) {
    extern __shared__ float smf[];
    const uint32_t sb = smem_u32(smf);
    const int tid = threadIdx.x, lane = tid & 31, wid = tid >> 5;
    const int gq = lane >> 2, tig = lane & 3;
    const int wm = wid >> 1, wn = wid & 1;
    zprep_tile(smf, sb, img, zwr, blockIdx.x, blockIdx.y * 128,
               tid, wm, wn, gq, tig);
}

// ---------------------------------------------------------------------------
// shared epilogue: shuffle cell update + writebacks (acc already holds gates)
// ---------------------------------------------------------------------------
__device__ __forceinline__ void step_epilogue(
    float acc[2][4][4], float* smf,
    float* hnext, float* out, int t_out, int TOUT,
    int j, int n0, int tid, int lane, int wid, int wm, int wn, int gq, int tig) {

    float* H2 = smf + OFF_A;            // 16 units x H_STR (aliases A bufs)
    const int mymt = tig & 1;
    const int r0e = wm * 32 + mymt * 16 + gq;
    #pragma unroll
    for (int nt = 0; nt < 4; nt++) {
        const int u = wn * 8 + nt * 2 + (tig >> 1);
        float oth[4];
        #pragma unroll
        for (int e = 0; e < 4; e++)
            oth[e] = __shfl_xor_sync(0xffffffffu, acc[mymt ^ 1][nt][e], 1);
        const float b0 = smf[OFF_BIAS + 4 * u + 0];
        const float b1 = smf[OFF_BIAS + 4 * u + 1];
        const float b2 = smf[OFF_BIAS + 4 * u + 2];
        const float b3 = smf[OFF_BIAS + 4 * u + 3];
        #pragma unroll
        for (int e2 = 0; e2 < 2; e2++) {
            const float ow0 = acc[mymt][nt][2 * e2], ow1 = acc[mymt][nt][2 * e2 + 1];
            const float ot0 = oth[2 * e2],           ot1 = oth[2 * e2 + 1];
            float gi, gf, gg, go;
            if (mymt == 0) { gi = ow0; gf = ow1; gg = ot0; go = ot1; }
            else           { gg = ow0; go = ow1; gi = ot0; gf = ot1; }
            gi += b0; gf += b1; gg += b2; go += b3;
            const int row = r0e + 8 * e2;
            const size_t ci = (size_t)(j * 16 + u) * NB + n0 + row;
            const float cold = g_Cbuf[ci];
            const float cn = sigf(gf) * cold + sigf(gi) * tanhf_(gg);
            g_Cbuf[ci] = cn;
            H2[u * H_STR + row] = sigf(go) * tanhf_(cn);
        }
    }
    __syncthreads();

    #pragma unroll
    for (int q = 0; q < 2; q++) {
        const int u = wid * 2 + q;
        #pragma unroll
        for (int mk = 0; mk < 4; mk++) {
            const int m = mk * 32 + lane;
            hnext[(size_t)(j * 16 + u) * NB + n0 + m] =
                __uint_as_float(rna_tf32(H2[u * H_STR + m]));
        }
    }
    const int hh = lane & 15, rp = lane >> 4;
    #pragma unroll
    for (int i2 = 0; i2 < 8; i2++) {
        const int mr = wid * 16 + i2 * 2 + rp;
        out[(size_t)(n0 + mr) * TOUT * HD + (size_t)t_out * HD + j * 16 + hh] =
            H2[hh * H_STR + mr];
    }
}

// ---------------------------------------------------------------------------
// phase-1 kernel: acc := Z[t&1] (L2-hot ring), acc += h@Whh, epilogue;
// then deep-pipelined zprep of img[t+1] into Z[(t+1)&1].
// ---------------------------------------------------------------------------
__global__ void __launch_bounds__(256, 2)
lstm_step_p1(const float* __restrict__ zrd,
             float* __restrict__ zwr,
             const float* __restrict__ imgnext,
             const float* __restrict__ hprev,
             float* __restrict__ hnext,
             float* __restrict__ out, int t_out, int TOUT) {
    extern __shared__ float smf[];
    const uint32_t sb = smem_u32(smf);
    const int tid = threadIdx.x, lane = tid & 31, wid = tid >> 5;
    const int gq = lane >> 2, tig = lane & 3;
    const int wm = wid >> 1, wn = wid & 1;
    const int j = blockIdx.x, n0 = blockIdx.y * 128;

    if (tid < 64) smf[OFF_BIAS + tid] = g_bias[j * 64 + tid];

    // acc := Z (LDGs into accumulator registers; ring slot is L2-hot)
    float acc[2][4][4];
    {
        const float* zb = zrd + (size_t)(j * 64) * NB + n0;
        #pragma unroll
        for (int mt = 0; mt < 2; mt++) {
            const int r0 = wm * 32 + mt * 16 + gq;
            #pragma unroll
            for (int nt = 0; nt < 4; nt++) {
                const int c0 = wn * 32 + nt * 8 + 2 * tig;
                acc[mt][nt][0] = zb[(size_t)(c0    ) * NB + r0    ];
                acc[mt][nt][1] = zb[(size_t)(c0 + 1) * NB + r0    ];
                acc[mt][nt][2] = zb[(size_t)(c0    ) * NB + r0 + 8];
                acc[mt][nt][3] = zb[(size_t)(c0 + 1) * NB + r0 + 8];
            }
        }
    }

    gemm_hot(acc, smf, sb, hprev, g_Whh, j, n0, tid, wm, wn, gq, tig);
    step_epilogue(acc, smf, hnext, out, t_out, TOUT,
                  j, n0, tid, lane, wid, wm, wn, gq, tig);
    __syncthreads();       // H2 (A bufs) fully consumed before zprep reuses

    if (imgnext != nullptr)
        zprep_tile(smf, sb, imgnext, zwr, j, n0, tid, wm, wn, gq, tig);
}

// ---------------------------------------------------------------------------
// phase-2 kernel: gates = h @ Wsum^T + b
// ---------------------------------------------------------------------------
__global__ void __launch_bounds__(256, 2)
lstm_step_p2(const float* __restrict__ hprev, float* __restrict__ hnext,
             float* __restrict__ out, int t_out, int TOUT) {
    extern __shared__ float smf[];
    const uint32_t sb = smem_u32(smf);
    const int tid = threadIdx.x, lane = tid & 31, wid = tid >> 5;
    const int gq = lane >> 2, tig = lane & 3;
    const int wm = wid >> 1, wn = wid & 1;
    const int j = blockIdx.x, n0 = blockIdx.y * 128;

    if (tid < 64) smf[OFF_BIAS + tid] = g_bias[j * 64 + tid];

    float acc[2][4][4];
    #pragma unroll
    for (int a0 = 0; a0 < 2; a0++)
        #pragma unroll
        for (int a1 = 0; a1 < 4; a1++)
            #pragma unroll
            for (int a2 = 0; a2 < 4; a2++) acc[a0][a1][a2] = 0.0f;

    gemm_hot(acc, smf, sb, hprev, g_Wsum, j, n0, tid, wm, wn, gq, tig);
    step_epilogue(acc, smf, hnext, out, t_out, TOUT,
                  j, n0, tid, lane, wid, wm, wn, gq, tig);
}

// ---------------------------------------------------------------------------
// launch: prep + zprep0 + 60 fused (step+zprep) + 54 plain steps
// ---------------------------------------------------------------------------
extern "C" void kernel_launch(void* const* d_in, const int* in_sizes, int n_in,
                              void* d_out, int out_size) {
    const float* img = (const float*)d_in[0];
    const float* Wih = (const float*)d_in[2];
    const float* Whh = (const float*)d_in[3];
    const float* bih = (const float*)d_in[4];
    const float* bhh = (const float*)d_in[5];
    float* out = (float*)d_out;

    const int T    = in_sizes[0] / (HD * NB);       // 60
    const int TOUT = out_size / (NB * HD);          // 114

    void *h0p, *h1p, *zp;
    cudaGetSymbolAddress(&h0p, g_Hbuf0);
    cudaGetSymbolAddress(&h1p, g_Hbuf1);
    cudaGetSymbolAddress(&zp, g_Z);
    float* hb[2] = {(float*)h0p, (float*)h1p};
    float* zs = (float*)zp;                         // 2 slots of NG*NB

    cudaFuncSetAttribute((const void*)zprep0_kernel,
                         cudaFuncAttributeMaxDynamicSharedMemorySize, SM_BYTES);
    cudaFuncSetAttribute((const void*)lstm_step_p1,
                         cudaFuncAttributeMaxDynamicSharedMemorySize, SM_BYTES);
    cudaFuncSetAttribute((const void*)lstm_step_p2,
                         cudaFuncAttributeMaxDynamicSharedMemorySize, SM_BYTES);

    prep_kernel<<<256, 256>>>(Wih, Whh, bih, bhh);

    dim3 grid(8, NB / 128);                         // 256 CTAs, 2/SM
    zprep0_kernel<<<grid, 256, SM_BYTES>>>(img, zs);   // Z slot 0 = t0

    for (int t = 0; t < TOUT; t++) {
        float* hp = hb[t & 1];
        float* hn = hb[(t + 1) & 1];
        if (t < T) {
            const float* nxt = (t + 1 < T) ? img + (size_t)(t + 1) * HD * NB
                                           : nullptr;
            lstm_step_p1<<<grid, 256, SM_BYTES>>>(
                zs + (size_t)(t & 1) * NG * NB,
                zs + (size_t)((t + 1) & 1) * NG * NB,
                nxt, hp, hn, out, t, TOUT);
        } else {
            lstm_step_p2<<<grid, 256, SM_BYTES>>>(hp, hn, out, t, TOUT);
        }
    }
}

// round 17
// speedup vs baseline: 1.5525x; 1.0342x over previous
#include <cuda_runtime.h>
#include <cstdint>

// ============================================================================
// LSTM_34883724378521 : T=60, C=H=128, N=4096, TOUT=114
// r9 base (best): fused tf32 mma.sync step, grid (8 x 32), 256 thr, 2 CTAs/SM,
// CTA tile M=128 x N=64, phase-1 chunk order h-first / img-last, 4-buf pipe.
// NEW: each phase-1 step WARMS L2 with the entire img[t+1] slice via cp.async
// into throwaway smem scratch (8 KB/CTA) -> next step's img chunks are L2-hot.
// ============================================================================
#define NB 4096
#define HD 128
#define NG 512

__device__ __forceinline__ uint32_t smem_u32(const void* p) {
    uint32_t a;
    asm("{ .reg .u64 t; cvta.to.shared.u64 t, %1; cvt.u32.u64 %0, t; }"
        : "=r"(a) : "l"(p));
    return a;
}
__device__ __forceinline__ void cp16(uint32_t dst, const void* src) {
    asm volatile("cp.async.cg.shared.global [%0], [%1], 16;" :: "r"(dst), "l"(src));
}
#define CP_COMMIT() asm volatile("cp.async.commit_group;" ::: "memory")
#define CP_WAIT(n)  asm volatile("cp.async.wait_group %0;" :: "n"(n) : "memory")

__device__ __forceinline__ uint32_t rna_tf32(float v) {
    uint32_t u; asm("cvt.rna.tf32.f32 %0, %1;" : "=r"(u) : "f"(v)); return u;
}
__device__ __forceinline__ void mma8(float* d, const uint32_t* a, const uint32_t* b) {
    asm volatile(
        "mma.sync.aligned.m16n8k8.row.col.f32.tf32.tf32.f32 "
        "{%0,%1,%2,%3}, {%4,%5,%6,%7}, {%8,%9}, {%0,%1,%2,%3};"
        : "+f"(d[0]), "+f"(d[1]), "+f"(d[2]), "+f"(d[3])
        : "r"(a[0]), "r"(a[1]), "r"(a[2]), "r"(a[3]), "r"(b[0]), "r"(b[1]));
}
__device__ __forceinline__ float sigf(float x)   { return 1.0f / (1.0f + __expf(-x)); }
__device__ __forceinline__ float tanhf_(float x) { return 1.0f - 2.0f / (__expf(2.0f * x) + 1.0f); }

// ---------------------------------------------------------------------------
// persistent device state
// ---------------------------------------------------------------------------
__device__ float g_Hbuf0[HD * NB];   // h state, h-major [H][N] (tf32-rounded)
__device__ float g_Hbuf1[HD * NB];
__device__ float g_Cbuf [HD * NB];   // c state, h-major
__device__ float g_W1[NG * 256];     // permuted [4h+g][h|x]  (h cols first)
__device__ float g_W2[NG * 128];     // permuted (W_ih+W_hh), tf32-rounded
__device__ float g_bias[NG];         // permuted b_ih + b_hh

// ---------------------------------------------------------------------------
// prep: row perm r = 4*h+g <- g*128+h. W1 cols: k<128 -> W_hh (h part first),
// k>=128 -> W_ih (img). RNA-round; zero state. (identical to round-9)
// ---------------------------------------------------------------------------
__global__ void prep_kernel(const float* __restrict__ Wih, const float* __restrict__ Whh,
                            const float* __restrict__ bih, const float* __restrict__ bhh) {
    int tid = blockIdx.x * 256 + threadIdx.x;       // 512*256 = 131072
    int r = tid >> 8, k = tid & 255;
    int h = r >> 2, g = r & 3;
    int orig = g * HD + h;
    float v = (k < 128) ? Whh[orig * HD + k] : Wih[orig * HD + (k - 128)];
    g_W1[r * 256 + k] = __uint_as_float(rna_tf32(v));
    if (k < 128)
        g_W2[r * 128 + k] =
            __uint_as_float(rna_tf32(Wih[orig * HD + k] + Whh[orig * HD + k]));
    if (k == 0) g_bias[r] = bih[orig] + bhh[orig];
    for (int i = tid; i < HD * NB; i += 131072) {
        g_Hbuf0[i] = 0.0f;
        g_Cbuf[i]  = 0.0f;
    }
}

// ---------------------------------------------------------------------------
// smem layout (float offsets): bias(64) | 4x A(32x136) | 4x B(64x36) | scratch
// H2 stage (16 x 130) aliases A buffer 0 after the mainloop.
// ---------------------------------------------------------------------------
static constexpr int A_STR = 136, B_STR = 36, H_STR = 130;
static constexpr int A_FL  = 32 * A_STR;      // 4352
static constexpr int B_FL  = 64 * B_STR;      // 2304
static constexpr int OFF_BIAS = 0;
static constexpr int OFF_A    = 64;
static constexpr int OFF_B    = OFF_A + 4 * A_FL;
static constexpr int OFF_SCR  = OFF_B + 4 * B_FL;    // 26688 (2048 floats)
static constexpr int SM_FLOATS = OFF_SCR + 2048;     // 28736
static constexpr int SM_BYTES  = SM_FLOATS * 4;      // 114944 B -> 2 CTAs/SM

// ---------------------------------------------------------------------------
// fused step. CTA tile M=128 x N=64 (16 hidden units), K = NCH*32.
// Phase 1 (NCH=8): chunks 0-3 = h (W_hh cols), chunks 4-7 = img (W_ih cols).
// ---------------------------------------------------------------------------
template <int NCH>
__global__ void __launch_bounds__(256, 2)
lstm_step(const float* __restrict__ xsrc,     // [128][NB] x_t slice or null
          const float* __restrict__ imgnext,  // img[t+1] slice: L2 warm target
          const float* __restrict__ hprev,    // [128][NB] (pre-rounded tf32)
          float* __restrict__ hnext,
          float* __restrict__ out, int t_out, int TOUT) {
    extern __shared__ float smf[];
    const uint32_t sb = smem_u32(smf);
    const int tid = threadIdx.x, lane = tid & 31, wid = tid >> 5;
    const int gq = lane >> 2, tig = lane & 3;
    const int wm = wid >> 1, wn = wid & 1;            // 4 x 2 warp grid
    const int j = blockIdx.x, n0 = blockIdx.y * 128;  // j: 64 gate cols

    if (tid < 64) smf[OFF_BIAS + tid] = g_bias[j * 64 + tid];

    const float* W = (NCH == 8) ? g_W1 : g_W2;
    const int KT = NCH * 32;

    auto loadC = [&](int ch) {
        const int buf = ch & 3;
        // h chunks first (L2-warm), img chunks last (warmed by previous step)
        const float* asrc = (NCH == 8 && ch >= 4) ? xsrc : hprev;
        const int kr = (NCH == 8 && ch >= 4) ? (ch - 4) * 32 : ch * 32;
        const uint32_t ab = sb + (uint32_t)(OFF_A + buf * A_FL) * 4;
        const uint32_t bb = sb + (uint32_t)(OFF_B + buf * B_FL) * 4;
        #pragma unroll
        for (int it = 0; it < 4; it++) {   // A: 32 k-rows x 128 m
            int idx = tid + it * 256;
            int kk = idx >> 5, mp = (idx & 31) << 2;
            cp16(ab + (uint32_t)(kk * A_STR + mp) * 4,
                 asrc + (size_t)(kr + kk) * NB + n0 + mp);
        }
        #pragma unroll
        for (int it = 0; it < 2; it++) {   // B: 64 gate-cols x 32 k
            int idx = tid + it * 256;
            int n = idx >> 3, q = (idx & 7) << 2;
            cp16(bb + (uint32_t)(n * B_STR + q) * 4,
                 W + (size_t)(j * 64 + n) * KT + ch * 32 + q);
        }
        // L2-warm the ENTIRE img[t+1] slice (8 KB per CTA, disjoint coverage).
        // Folded into chunk-0's commit group; data is throwaway, the L2 fill
        // is the point. cp.async (unlike prefetch) cannot be dropped.
        if (NCH == 8 && ch == 0 && imgnext != nullptr) {
            const size_t segf = (size_t)(blockIdx.y * 8 + blockIdx.x) * 2048;
            #pragma unroll
            for (int it = 0; it < 2; it++)
                cp16(sb + (uint32_t)(OFF_SCR + it * 1024 + tid * 4) * 4,
                     imgnext + segf + it * 1024 + tid * 4);
        }
        CP_COMMIT();
    };

    float acc[2][4][4];
    #pragma unroll
    for (int a0 = 0; a0 < 2; a0++)
        #pragma unroll
        for (int a1 = 0; a1 < 4; a1++)
            #pragma unroll
            for (int a2 = 0; a2 < 4; a2++) acc[a0][a1][a2] = 0.0f;

    loadC(0);
    loadC(1);
    loadC(2);
    #pragma unroll
    for (int ch = 0; ch < NCH; ch++) {
        const int rem = NCH - 1 - ch;
        if (rem >= 2)      { CP_WAIT(2); }
        else if (rem == 1) { CP_WAIT(1); }
        else               { CP_WAIT(0); }
        __syncthreads();                   // chunk ch ready; mma(ch-1) done
        if (ch + 3 < NCH) loadC(ch + 3);   // writes buf (ch+3)&3 — free
        const float* As = smf + OFF_A + (ch & 3) * A_FL;
        const float* Bs = smf + OFF_B + (ch & 3) * B_FL;
        const bool docvt = (NCH == 8 && ch >= 4);   // img chunks need rounding

        #pragma unroll
        for (int kc = 0; kc < 4; kc++) {
            const int k0 = kc * 8;
            uint32_t a[2][4];
            #pragma unroll
            for (int mt = 0; mt < 2; mt++) {
                const int r0 = wm * 32 + mt * 16 + gq;
                float v0 = As[(k0 + tig) * A_STR + r0];
                float v1 = As[(k0 + tig) * A_STR + r0 + 8];
                float v2 = As[(k0 + tig + 4) * A_STR + r0];
                float v3 = As[(k0 + tig + 4) * A_STR + r0 + 8];
                if (docvt) {
                    a[mt][0] = rna_tf32(v0); a[mt][1] = rna_tf32(v1);
                    a[mt][2] = rna_tf32(v2); a[mt][3] = rna_tf32(v3);
                } else {
                    a[mt][0] = __float_as_uint(v0); a[mt][1] = __float_as_uint(v1);
                    a[mt][2] = __float_as_uint(v2); a[mt][3] = __float_as_uint(v3);
                }
            }
            #pragma unroll
            for (int nt = 0; nt < 4; nt++) {
                const int c0 = wn * 32 + nt * 8 + gq;
                uint32_t b[2];
                b[0] = __float_as_uint(Bs[c0 * B_STR + k0 + tig]);
                b[1] = __float_as_uint(Bs[c0 * B_STR + k0 + tig + 4]);
                mma8(acc[0][nt], a[0], b);
                mma8(acc[1][nt], a[1], b);
            }
        }
    }
    __syncthreads();     // all mma done -> A bufs reusable as H2 stage

    // ---- shuffle epilogue: pair (i,f) with (g,o) via lane^1 ----
    float* H2 = smf + OFF_A;            // 16 units x H_STR
    const int mymt = tig & 1;
    const int r0e = wm * 32 + mymt * 16 + gq;
    #pragma unroll
    for (int nt = 0; nt < 4; nt++) {
        const int u = wn * 8 + nt * 2 + (tig >> 1);
        float oth[4];
        #pragma unroll
        for (int e = 0; e < 4; e++)
            oth[e] = __shfl_xor_sync(0xffffffffu, acc[mymt ^ 1][nt][e], 1);
        const float b0 = smf[OFF_BIAS + 4 * u + 0];
        const float b1 = smf[OFF_BIAS + 4 * u + 1];
        const float b2 = smf[OFF_BIAS + 4 * u + 2];
        const float b3 = smf[OFF_BIAS + 4 * u + 3];
        #pragma unroll
        for (int e2 = 0; e2 < 2; e2++) {
            const float ow0 = acc[mymt][nt][2 * e2], ow1 = acc[mymt][nt][2 * e2 + 1];
            const float ot0 = oth[2 * e2],           ot1 = oth[2 * e2 + 1];
            float gi, gf, gg, go;
            if (mymt == 0) { gi = ow0; gf = ow1; gg = ot0; go = ot1; }
            else           { gg = ow0; go = ow1; gi = ot0; gf = ot1; }
            gi += b0; gf += b1; gg += b2; go += b3;
            const int row = r0e + 8 * e2;
            const size_t ci = (size_t)(j * 16 + u) * NB + n0 + row;
            const float cold = g_Cbuf[ci];
            const float cn = sigf(gf) * cold + sigf(gi) * tanhf_(gg);
            g_Cbuf[ci] = cn;
            H2[u * H_STR + row] = sigf(go) * tanhf_(cn);
        }
    }
    __syncthreads();

    // ---- h-state writeback (h-major, pre-rounded to tf32) ----
    #pragma unroll
    for (int q = 0; q < 2; q++) {
        const int u = wid * 2 + q;
        #pragma unroll
        for (int mk = 0; mk < 4; mk++) {
            const int m = mk * 32 + lane;
            hnext[(size_t)(j * 16 + u) * NB + n0 + m] =
                __uint_as_float(rna_tf32(H2[u * H_STR + m]));
        }
    }
    // ---- output: out[n][t][h], 64B contiguous (16 h per CTA) ----
    const int hh = lane & 15, rp = lane >> 4;
    #pragma unroll
    for (int i2 = 0; i2 < 8; i2++) {
        const int mr = wid * 16 + i2 * 2 + rp;
        out[(size_t)(n0 + mr) * TOUT * HD + (size_t)t_out * HD + j * 16 + hh] =
            H2[hh * H_STR + mr];
    }
}

// ---------------------------------------------------------------------------
// launch: prep + 60 K=256 steps (with img[t+1] L2 warming) + 54 K=128 steps
// ---------------------------------------------------------------------------
extern "C" void kernel_launch(void* const* d_in, const int* in_sizes, int n_in,
                              void* d_out, int out_size) {
    const float* img = (const float*)d_in[0];
    const float* Wih = (const float*)d_in[2];
    const float* Whh = (const float*)d_in[3];
    const float* bih = (const float*)d_in[4];
    const float* bhh = (const float*)d_in[5];
    float* out = (float*)d_out;

    const int T    = in_sizes[0] / (HD * NB);       // 60
    const int TOUT = out_size / (NB * HD);          // 114

    void *h0p, *h1p;
    cudaGetSymbolAddress(&h0p, g_Hbuf0);
    cudaGetSymbolAddress(&h1p, g_Hbuf1);
    float* hb[2] = {(float*)h0p, (float*)h1p};

    cudaFuncSetAttribute((const void*)lstm_step<8>,
                         cudaFuncAttributeMaxDynamicSharedMemorySize, SM_BYTES);
    cudaFuncSetAttribute((const void*)lstm_step<4>,
                         cudaFuncAttributeMaxDynamicSharedMemorySize, SM_BYTES);

    prep_kernel<<<512, 256>>>(Wih, Whh, bih, bhh);

    dim3 grid(8, NB / 128);                         // 256 CTAs, 2/SM
    for (int t = 0; t < TOUT; t++) {
        float* hp = hb[t & 1];
        float* hn = hb[(t + 1) & 1];
        if (t < T) {
            const float* nxt = (t + 1 < T) ? img + (size_t)(t + 1) * HD * NB
                                           : nullptr;
            lstm_step<8><<<grid, 256, SM_BYTES>>>(
                img + (size_t)t * HD * NB, nxt, hp, hn, out, t, TOUT);
        } else {
            lstm_step<4><<<grid, 256, SM_BYTES>>>(
                nullptr, nullptr, hp, hn, out, t, TOUT);
        }
    }
}